// round 4
// baseline (speedup 1.0000x reference)
#include <cuda_runtime.h>
#include <math.h>

#define HH 512
#define WW 512
#define HW 262144
#define NC 8192

// ---------------- scratch (device globals; no allocation allowed) ----------
__device__ float  g_buf1[48  * HW];
__device__ float  g_buf2[96  * HW];
__device__ float  g_buf3[128 * HW];
__device__ float  g_h1[NC * 256];
__device__ float  g_sh[NC * 128];
__device__ double g_gs[3][16];
__device__ double g_gq[3][16];
__device__ float  g_scale[128];
__device__ float  g_shift[128];
__device__ float  g_pooled[128];

// ---------------- zero-init ------------------------------------------------
// Must cover out[0 .. 262146]: grid (262144) + log_prob + entropy + value.
// log_prob/entropy are accumulated with atomicAdd, so missing them leaves
// 0xAA poison in the result.
__global__ void zero_kernel(float* __restrict__ out) {
    int i = blockIdx.x * blockDim.x + threadIdx.x;
    if (i < 262147) out[i] = 0.f;
    if (i < 48) {
        ((double*)g_gs)[i] = 0.0;
        ((double*)g_gq)[i] = 0.0;
    }
}

// ---------------- direct 3x3 conv (SAME), tiled ----------------------------
// block: (32,8) threads, each thread computes 4 vertical pixels x OCB ochans
// grid: (16,16, COUT/OCB)
template<int CIN, int OCB>
__launch_bounds__(256)
__global__ void conv3x3_kernel(const float* __restrict__ in,
                               const float* __restrict__ wt,
                               const float* __restrict__ bias,
                               float* __restrict__ out) {
    __shared__ float s_in[8][34][34];
    __shared__ float s_w[OCB][72];
    const int tx = threadIdx.x, ty = threadIdx.y;
    const int tid = ty * 32 + tx;
    const int x0 = blockIdx.x * 32, y0 = blockIdx.y * 32;
    const int ocb = blockIdx.z * OCB;

    float acc[4][OCB];
#pragma unroll
    for (int p = 0; p < 4; p++)
#pragma unroll
        for (int o = 0; o < OCB; o++) acc[p][o] = 0.f;

    for (int c0 = 0; c0 < CIN; c0 += 8) {
        const int cc = (CIN - c0 < 8) ? (CIN - c0) : 8;
        // load input tile (34x34 halo), zero-padded
        for (int idx = tid; idx < 8 * 34 * 34; idx += 256) {
            int ci  = idx / 1156;
            int rem = idx - ci * 1156;
            int r = rem / 34, s = rem - r * 34;
            float v = 0.f;
            int gy = y0 + r - 1, gx = x0 + s - 1;
            if (ci < cc && gy >= 0 && gy < HH && gx >= 0 && gx < WW)
                v = in[(size_t)(c0 + ci) * HW + gy * WW + gx];
            s_in[ci][r][s] = v;
        }
        // load weight chunk
        for (int idx = tid; idx < OCB * 72; idx += 256) {
            int o = idx / 72;
            int rem = idx - o * 72;
            int ci = rem / 9;
            int k = rem - ci * 9;
            float v = 0.f;
            if (ci < cc)
                v = wt[((size_t)(ocb + o) * CIN + c0 + ci) * 9 + k];
            s_w[o][rem] = v;
        }
        __syncthreads();

        for (int ci = 0; ci < 8; ci++) {
#pragma unroll
            for (int k = 0; k < 9; k++) {
                const int dy = k / 3, dx = k - dy * 3;
                float xv[4];
#pragma unroll
                for (int p = 0; p < 4; p++)
                    xv[p] = s_in[ci][ty * 4 + p + dy][tx + dx];
#pragma unroll
                for (int o = 0; o < OCB; o++) {
                    float wv = s_w[o][ci * 9 + k];
#pragma unroll
                    for (int p = 0; p < 4; p++)
                        acc[p][o] = fmaf(xv[p], wv, acc[p][o]);
                }
            }
        }
        __syncthreads();
    }

#pragma unroll
    for (int o = 0; o < OCB; o++) {
        float bv = bias[ocb + o];
#pragma unroll
        for (int p = 0; p < 4; p++) {
            int y = y0 + ty * 4 + p;
            out[(size_t)(ocb + o) * HW + y * WW + x0 + tx] = acc[p][o] + bv;
        }
    }
}

// ---------------- GroupNorm stats (sum / sumsq per group) ------------------
// grid: (C, 16) ; block 256
__global__ void gn_stats_kernel(const float* __restrict__ buf, int cpg, int layer) {
    __shared__ float sb[256];
    __shared__ float sq[256];
    const int c = blockIdx.x, slice = blockIdx.y;
    const float* p = buf + (size_t)c * HW + slice * 16384;
    float s = 0.f, q = 0.f;
    for (int e = threadIdx.x; e < 16384; e += 256) {
        float v = p[e];
        s += v; q += v * v;
    }
    sb[threadIdx.x] = s; sq[threadIdx.x] = q;
    __syncthreads();
    for (int st = 128; st > 0; st >>= 1) {
        if (threadIdx.x < st) {
            sb[threadIdx.x] += sb[threadIdx.x + st];
            sq[threadIdx.x] += sq[threadIdx.x + st];
        }
        __syncthreads();
    }
    if (threadIdx.x == 0) {
        int g = c / cpg;
        atomicAdd(&g_gs[layer][g], (double)sb[0]);
        atomicAdd(&g_gq[layer][g], (double)sq[0]);
    }
}

__global__ void gn_finalize_kernel(const float* __restrict__ gamma,
                                   const float* __restrict__ beta,
                                   int C, int cpg, int layer) {
    int c = threadIdx.x;
    if (c < C) {
        int g = c / cpg;
        double n = (double)cpg * (double)HW;
        double m = g_gs[layer][g] / n;
        double var = g_gq[layer][g] / n - m * m;
        float rs = (float)(1.0 / sqrt(var + 1e-5));
        float sc = gamma[c] * rs;
        g_scale[c] = sc;
        g_shift[c] = beta[c] - (float)m * sc;
    }
}

// float4-vectorized normalize + ReLU (HW is a multiple of 4)
__global__ void norm_relu_kernel(float* __restrict__ buf, int total4) {
    float4* b4 = reinterpret_cast<float4*>(buf);
    for (int i = blockIdx.x * blockDim.x + threadIdx.x; i < total4;
         i += gridDim.x * blockDim.x) {
        int c = i >> 16;               // (i*4) >> 18
        float sc = g_scale[c], sh = g_shift[c];
        float4 v = b4[i];
        v.x = fmaxf(0.f, fmaf(v.x, sc, sh));
        v.y = fmaxf(0.f, fmaf(v.y, sc, sh));
        v.z = fmaxf(0.f, fmaf(v.z, sc, sh));
        v.w = fmaxf(0.f, fmaf(v.w, sc, sh));
        b4[i] = v;
    }
}

// ---------------- global avg pool over f (128 ch) --------------------------
__global__ void pool_kernel(const float* __restrict__ f) {
    __shared__ float sb[256];
    const int c = blockIdx.x;
    const float* p = f + (size_t)c * HW;
    float s = 0.f;
    for (int i = threadIdx.x; i < HW; i += 256) s += p[i];
    sb[threadIdx.x] = s;
    __syncthreads();
    for (int st = 128; st > 0; st >>= 1) {
        if (threadIdx.x < st) sb[threadIdx.x] += sb[threadIdx.x + st];
        __syncthreads();
    }
    if (threadIdx.x == 0) g_pooled[c] = sb[0] * (1.0f / (float)HW);
}

__global__ void value_kernel(const float* __restrict__ vw1, const float* __restrict__ vb1,
                             const float* __restrict__ vw2, const float* __restrict__ vb2,
                             float* __restrict__ out) {
    __shared__ float h[64];
    int t = threadIdx.x;
    float s = vb1[t];
    for (int k = 0; k < 128; k++) s = fmaf(g_pooled[k], vw1[k * 64 + t], s);
    h[t] = fmaxf(s, 0.f);
    __syncthreads();
    if (t == 0) {
        float v = vb2[0];
        for (int k = 0; k < 64; k++) v = fmaf(h[k], vw2[k], v);
        out[262146] = v;
    }
}

// ---------------- MLP1: patch gather + (1152 -> 256) -----------------------
// 16 cells / block, 256 threads (one per output), dyn smem = 16*1152*4 = 73728
__global__ void mlp1_kernel(const float* __restrict__ f,
                            const int* __restrict__ ci_, const int* __restrict__ cj_,
                            const float* __restrict__ fw1, const float* __restrict__ fb1) {
    extern __shared__ float sp[];   // layout [k][cell] : sp[k*16 + cc]
    const int t = threadIdx.x;
    const int base = blockIdx.x * 16;

    for (int idx = t; idx < 16 * 1152; idx += 256) {
        int cc = idx / 1152;
        int k  = idx - cc * 1152;
        int c  = k / 9;
        int rr = k - c * 9;
        int r  = rr / 3, s2 = rr - r * 3;
        int y = ci_[base + cc] - 1 + r;
        int x = cj_[base + cc] - 1 + s2;
        float v = 0.f;
        if (y >= 0 && y < HH && x >= 0 && x < WW)
            v = f[(size_t)c * HW + y * WW + x];
        sp[k * 16 + cc] = v;
    }
    __syncthreads();

    float acc[16];
#pragma unroll
    for (int cc = 0; cc < 16; cc++) acc[cc] = 0.f;

    for (int k = 0; k < 1152; k++) {
        float wv = fw1[k * 256 + t];
        const float4* s4 = reinterpret_cast<const float4*>(sp + k * 16);
        float4 a0 = s4[0], a1 = s4[1], a2 = s4[2], a3 = s4[3];
        acc[0]  = fmaf(a0.x, wv, acc[0]);  acc[1]  = fmaf(a0.y, wv, acc[1]);
        acc[2]  = fmaf(a0.z, wv, acc[2]);  acc[3]  = fmaf(a0.w, wv, acc[3]);
        acc[4]  = fmaf(a1.x, wv, acc[4]);  acc[5]  = fmaf(a1.y, wv, acc[5]);
        acc[6]  = fmaf(a1.z, wv, acc[6]);  acc[7]  = fmaf(a1.w, wv, acc[7]);
        acc[8]  = fmaf(a2.x, wv, acc[8]);  acc[9]  = fmaf(a2.y, wv, acc[9]);
        acc[10] = fmaf(a2.z, wv, acc[10]); acc[11] = fmaf(a2.w, wv, acc[11]);
        acc[12] = fmaf(a3.x, wv, acc[12]); acc[13] = fmaf(a3.y, wv, acc[13]);
        acc[14] = fmaf(a3.z, wv, acc[14]); acc[15] = fmaf(a3.w, wv, acc[15]);
    }
    float bv = fb1[t];
#pragma unroll
    for (int cc = 0; cc < 16; cc++)
        g_h1[(size_t)(base + cc) * 256 + t] = fmaxf(acc[cc] + bv, 0.f);
}

// ---------------- MLP2: (256 -> 128) ---------------------------------------
// 16 cells / block, 128 threads
__global__ void mlp2_kernel(const float* __restrict__ fw2, const float* __restrict__ fb2) {
    __shared__ float sh1[256 * 16];   // [k][cell]
    const int t = threadIdx.x;
    const int base = blockIdx.x * 16;
    for (int idx = t; idx < 16 * 256; idx += 128) {
        int cc = idx >> 8;
        int k  = idx & 255;
        sh1[k * 16 + cc] = g_h1[(size_t)(base + cc) * 256 + k];
    }
    __syncthreads();

    float acc[16];
#pragma unroll
    for (int cc = 0; cc < 16; cc++) acc[cc] = 0.f;

    for (int k = 0; k < 256; k++) {
        float wv = fw2[k * 128 + t];
        const float4* s4 = reinterpret_cast<const float4*>(sh1 + k * 16);
        float4 a0 = s4[0], a1 = s4[1], a2 = s4[2], a3 = s4[3];
        acc[0]  = fmaf(a0.x, wv, acc[0]);  acc[1]  = fmaf(a0.y, wv, acc[1]);
        acc[2]  = fmaf(a0.z, wv, acc[2]);  acc[3]  = fmaf(a0.w, wv, acc[3]);
        acc[4]  = fmaf(a1.x, wv, acc[4]);  acc[5]  = fmaf(a1.y, wv, acc[5]);
        acc[6]  = fmaf(a1.z, wv, acc[6]);  acc[7]  = fmaf(a1.w, wv, acc[7]);
        acc[8]  = fmaf(a2.x, wv, acc[8]);  acc[9]  = fmaf(a2.y, wv, acc[9]);
        acc[10] = fmaf(a2.z, wv, acc[10]); acc[11] = fmaf(a2.w, wv, acc[11]);
        acc[12] = fmaf(a3.x, wv, acc[12]); acc[13] = fmaf(a3.y, wv, acc[13]);
        acc[14] = fmaf(a3.z, wv, acc[14]); acc[15] = fmaf(a3.w, wv, acc[15]);
    }
    float bv = fb2[t];
#pragma unroll
    for (int cc = 0; cc < 16; cc++)
        g_sh[(size_t)(base + cc) * 128 + t] = fmaxf(acc[cc] + bv, 0.f);
}

// ---------------- heads: 3 linear heads + logprob/entropy + scatter --------
// 64 cells / block, 256 threads (4 per cell), grid 128
__global__ void heads_kernel(const int* __restrict__ ci_, const int* __restrict__ cj_,
                             const int* __restrict__ act,
                             const float* __restrict__ bw, const float* __restrict__ bb,
                             const float* __restrict__ iw, const float* __restrict__ ib,
                             const float* __restrict__ tw, const float* __restrict__ tb,
                             float* __restrict__ out) {
    __shared__ float ssh[64][129];
    __shared__ float swb[512], swi[512], swt[512];
    __shared__ float red[256];
    const int t = threadIdx.x;
    const int base = blockIdx.x * 64;

    for (int idx = t; idx < 64 * 128; idx += 256) {
        int cc = idx >> 7, k = idx & 127;
        ssh[cc][k] = g_sh[(size_t)(base + cc) * 128 + k];
    }
    for (int idx = t; idx < 512; idx += 256) {
        swb[idx] = bw[idx]; swi[idx] = iw[idx]; swt[idx] = tw[idx];
    }
    __syncthreads();

    const int cell = t >> 2, j = t & 3;
    float sb = bb[j], si = ib[j], st = tb[j];
    for (int k = 0; k < 128; k++) {
        float v = ssh[cell][k];
        sb = fmaf(v, swb[k * 4 + j], sb);
        si = fmaf(v, swi[k * 4 + j], si);
        st = fmaf(v, swt[k * 4 + j], st);
    }
    const int gcell = base + cell;
    out[262147 + gcell * 4 + j] = si;
    out[294915 + gcell * 4 + j] = st;

    float p = 1.f / (1.f + expf(-sb));
    p = fminf(fmaxf(p, 1e-7f), 1.f - 1e-7f);
    float a = (float)act[gcell * 4 + j];
    float lp = a * logf(p) + (1.f - a) * logf(1.f - p);
    float en = -(p * logf(p) + (1.f - p) * logf(1.f - p));

    // scatter at N/E/S/W neighbor
    const int di4[4] = {-1, 0, 1, 0};
    const int dj4[4] = {0, 1, 0, -1};
    int ii = ci_[gcell], jj = cj_[gcell];
    int ni = ii + di4[j], nj = jj + dj4[j];
    if (a > 0.5f && ni >= 0 && ni < HH && nj >= 0 && nj < WW)
        out[ni * WW + nj] = 1.0f;

    // block reductions for log_prob / entropy
    red[t] = lp;
    __syncthreads();
    for (int s = 128; s > 0; s >>= 1) {
        if (t < s) red[t] += red[t + s];
        __syncthreads();
    }
    if (t == 0) atomicAdd(&out[262144], red[0]);
    __syncthreads();
    red[t] = en;
    __syncthreads();
    for (int s = 128; s > 0; s >>= 1) {
        if (t < s) red[t] += red[t + s];
        __syncthreads();
    }
    if (t == 0) atomicAdd(&out[262145], red[0]);
}

// ---------------- launch ----------------------------------------------------
extern "C" void kernel_launch(void* const* d_in, const int* in_sizes, int n_in,
                              void* d_out, int out_size) {
    const float* x      = (const float*)d_in[0];
    const int*   cell_i = (const int*)d_in[1];
    const int*   cell_j = (const int*)d_in[2];
    const int*   action = (const int*)d_in[3];
    const float* w1 = (const float*)d_in[4];
    const float* b1 = (const float*)d_in[5];
    const float* g1 = (const float*)d_in[6];
    const float* be1 = (const float*)d_in[7];
    const float* w2 = (const float*)d_in[8];
    const float* b2 = (const float*)d_in[9];
    const float* g2 = (const float*)d_in[10];
    const float* be2 = (const float*)d_in[11];
    const float* w3 = (const float*)d_in[12];
    const float* b3 = (const float*)d_in[13];
    const float* g3 = (const float*)d_in[14];
    const float* be3 = (const float*)d_in[15];
    const float* fw1 = (const float*)d_in[16];
    const float* fb1 = (const float*)d_in[17];
    const float* fw2 = (const float*)d_in[18];
    const float* fb2 = (const float*)d_in[19];
    const float* bw = (const float*)d_in[20];
    const float* bb = (const float*)d_in[21];
    const float* iw = (const float*)d_in[22];
    const float* ib = (const float*)d_in[23];
    const float* tw = (const float*)d_in[24];
    const float* tb = (const float*)d_in[25];
    const float* vw1 = (const float*)d_in[26];
    const float* vb1 = (const float*)d_in[27];
    const float* vw2 = (const float*)d_in[28];
    const float* vb2 = (const float*)d_in[29];
    float* out = (float*)d_out;

    float* buf1; cudaGetSymbolAddress((void**)&buf1, g_buf1);
    float* buf2; cudaGetSymbolAddress((void**)&buf2, g_buf2);
    float* buf3; cudaGetSymbolAddress((void**)&buf3, g_buf3);

    // 1025 blocks: covers out[0..262146] (grid + log_prob + entropy + value)
    zero_kernel<<<1025, 256>>>(out);

    // layer 1: 14 -> 48, GN(6)
    conv3x3_kernel<14, 16><<<dim3(16, 16, 3), dim3(32, 8)>>>(x, w1, b1, buf1);
    gn_stats_kernel<<<dim3(48, 16), 256>>>(buf1, 8, 0);
    gn_finalize_kernel<<<1, 128>>>(g1, be1, 48, 8, 0);
    norm_relu_kernel<<<2048, 256>>>(buf1, 48 * HW / 4);

    // layer 2: 48 -> 96, GN(12)
    conv3x3_kernel<48, 16><<<dim3(16, 16, 6), dim3(32, 8)>>>(buf1, w2, b2, buf2);
    gn_stats_kernel<<<dim3(96, 16), 256>>>(buf2, 8, 1);
    gn_finalize_kernel<<<1, 128>>>(g2, be2, 96, 8, 1);
    norm_relu_kernel<<<2048, 256>>>(buf2, 96 * HW / 4);

    // layer 3: 96 -> 128, GN(16)
    conv3x3_kernel<96, 16><<<dim3(16, 16, 8), dim3(32, 8)>>>(buf2, w3, b3, buf3);
    gn_stats_kernel<<<dim3(128, 16), 256>>>(buf3, 8, 2);
    gn_finalize_kernel<<<1, 128>>>(g3, be3, 128, 8, 2);
    norm_relu_kernel<<<2048, 256>>>(buf3, 128 * HW / 4);

    // value head
    pool_kernel<<<128, 256>>>(buf3);
    value_kernel<<<1, 64>>>(vw1, vb1, vw2, vb2, out);

    // per-cell MLP
    cudaFuncSetAttribute(mlp1_kernel, cudaFuncAttributeMaxDynamicSharedMemorySize, 73728);
    mlp1_kernel<<<512, 256, 73728>>>(buf3, cell_i, cell_j, fw1, fb1);
    mlp2_kernel<<<512, 128>>>(fw2, fb2);
    heads_kernel<<<128, 256>>>(cell_i, cell_j, action, bw, bb, iw, ib, tw, tb, out);
}

// round 11
// speedup vs baseline: 1.0416x; 1.0416x over previous
#include <cuda_runtime.h>
#include <stdint.h>
#include <math.h>

#define HH 512
#define WW 512
#define HW 262144
#define NC 8192

// ---------------- scratch (device globals; no allocation allowed) ----------
__device__ float  g_buf1[48  * HW];
__device__ float  g_buf2[96  * HW];
__device__ float  g_buf3[128 * HW];
__device__ float  g_h1[NC * 256];
__device__ float  g_sh[NC * 128];
__device__ double g_gs[3][16];
__device__ double g_gq[3][16];
__device__ float  g_scaleL[3 * 128];
__device__ float  g_shiftL[3 * 128];
__device__ float  g_pooled[128];

// ---------------- zero-init ------------------------------------------------
__global__ void zero_kernel(float* __restrict__ out) {
    int i = blockIdx.x * blockDim.x + threadIdx.x;
    if (i < 262147) out[i] = 0.f;
    if (i < 48) {
        ((double*)g_gs)[i] = 0.0;
        ((double*)g_gq)[i] = 0.0;
    }
}

// ---------------- direct 3x3 conv (layer 1 only: 14 -> 48) -----------------
template<int CIN, int OCB>
__launch_bounds__(256)
__global__ void conv3x3_kernel(const float* __restrict__ in,
                               const float* __restrict__ wt,
                               const float* __restrict__ bias,
                               float* __restrict__ out) {
    __shared__ float s_in[8][34][34];
    __shared__ float s_w[OCB][72];
    const int tx = threadIdx.x, ty = threadIdx.y;
    const int tid = ty * 32 + tx;
    const int x0 = blockIdx.x * 32, y0 = blockIdx.y * 32;
    const int ocb = blockIdx.z * OCB;

    float acc[4][OCB];
#pragma unroll
    for (int p = 0; p < 4; p++)
#pragma unroll
        for (int o = 0; o < OCB; o++) acc[p][o] = 0.f;

    for (int c0 = 0; c0 < CIN; c0 += 8) {
        const int cc = (CIN - c0 < 8) ? (CIN - c0) : 8;
        for (int idx = tid; idx < 8 * 34 * 34; idx += 256) {
            int ci  = idx / 1156;
            int rem = idx - ci * 1156;
            int r = rem / 34, s = rem - r * 34;
            float v = 0.f;
            int gy = y0 + r - 1, gx = x0 + s - 1;
            if (ci < cc && gy >= 0 && gy < HH && gx >= 0 && gx < WW)
                v = in[(size_t)(c0 + ci) * HW + gy * WW + gx];
            s_in[ci][r][s] = v;
        }
        for (int idx = tid; idx < OCB * 72; idx += 256) {
            int o = idx / 72;
            int rem = idx - o * 72;
            int ci = rem / 9;
            int k = rem - ci * 9;
            float v = 0.f;
            if (ci < cc)
                v = wt[((size_t)(ocb + o) * CIN + c0 + ci) * 9 + k];
            s_w[o][rem] = v;
        }
        __syncthreads();

        for (int ci = 0; ci < 8; ci++) {
#pragma unroll
            for (int k = 0; k < 9; k++) {
                const int dy = k / 3, dx = k - dy * 3;
                float xv[4];
#pragma unroll
                for (int p = 0; p < 4; p++)
                    xv[p] = s_in[ci][ty * 4 + p + dy][tx + dx];
#pragma unroll
                for (int o = 0; o < OCB; o++) {
                    float wv = s_w[o][ci * 9 + k];
#pragma unroll
                    for (int p = 0; p < 4; p++)
                        acc[p][o] = fmaf(xv[p], wv, acc[p][o]);
                }
            }
        }
        __syncthreads();
    }

#pragma unroll
    for (int o = 0; o < OCB; o++) {
        float bv = bias[ocb + o];
#pragma unroll
        for (int p = 0; p < 4; p++) {
            int y = y0 + ty * 4 + p;
            out[(size_t)(ocb + o) * HW + y * WW + x0 + tx] = acc[p][o] + bv;
        }
    }
}

// ---------------- tf32x3 mma implicit-GEMM conv (layers 2,3) ---------------
// Split-precision: v = v_hi + v_lo (both tf32); acc += ah*bh + ah*bl + al*bh.
// Input staging applies previous layer's GN scale/shift + ReLU ONLY to
// in-bounds pixels (reference pads the normalized map with zeros).
#define SRS 267   // im2col row stride (words)
#define SAS 76    // weight row stride (words)
#define SMEM_MMA_BYTES ((2 * 32 * SAS + 2 * 8 * 3 * SRS) * 4)

__device__ __forceinline__ void mma_tf32(float* c, const uint32_t* a,
                                         uint32_t b0, uint32_t b1) {
    asm volatile(
        "mma.sync.aligned.m16n8k8.row.col.f32.tf32.tf32.f32 "
        "{%0,%1,%2,%3}, {%4,%5,%6,%7}, {%8,%9}, {%0,%1,%2,%3};"
        : "+f"(c[0]), "+f"(c[1]), "+f"(c[2]), "+f"(c[3])
        : "r"(a[0]), "r"(a[1]), "r"(a[2]), "r"(a[3]), "r"(b0), "r"(b1));
}

__device__ __forceinline__ uint32_t f2tf32(float v) {
    uint32_t u;
    asm("cvt.rna.tf32.f32 %0, %1;" : "=r"(u) : "f"(v));
    return u;
}

template<int CIN>
__launch_bounds__(256)
__global__ void conv_mma_kernel(const float* __restrict__ in,
                                const float* __restrict__ wt,
                                const float* __restrict__ bias,
                                const float* __restrict__ sc,
                                const float* __restrict__ sh,
                                float* __restrict__ out) {
    extern __shared__ uint32_t smem_u[];
    uint32_t* s_Ah = smem_u;                       // [32][SAS]
    uint32_t* s_Al = s_Ah + 32 * SAS;
    uint32_t* s_rh = s_Al + 32 * SAS;              // [24][SRS]
    uint32_t* s_rl = s_rh + 8 * 3 * SRS;

    const int tid = threadIdx.x;
    const int lane = tid & 31, w = tid >> 5;
    const int g = lane >> 2, tig = lane & 3;
    const int y = blockIdx.y, x0 = blockIdx.x * 256, ocb = blockIdx.z * 32;

    // per-thread im2col smem offsets for the 2 B-rows of each of 9 k-steps
    int off1[9], off2[9];
#pragma unroll
    for (int ks = 0; ks < 9; ks++) {
        int k1 = ks * 8 + tig, k2 = k1 + 4;
        int c1 = k1 / 9, t1 = k1 - c1 * 9, dy1 = t1 / 3, dx1 = t1 - dy1 * 3;
        int c2 = k2 / 9, t2 = k2 - c2 * 9, dy2 = t2 / 3, dx2 = t2 - dy2 * 3;
        off1[ks] = (c1 * 3 + dy1) * SRS + dx1;
        off2[ks] = (c2 * 3 + dy2) * SRS + dx2;
    }

    float acc[2][4][4];
#pragma unroll
    for (int mf = 0; mf < 2; mf++)
#pragma unroll
        for (int nf = 0; nf < 4; nf++)
#pragma unroll
            for (int e = 0; e < 4; e++) acc[mf][nf][e] = 0.f;

    for (int ci0 = 0; ci0 < CIN; ci0 += 8) {
        __syncthreads();
        // stage weights (hi/lo): 32 oc x 72 k
        for (int e = tid; e < 32 * 72; e += 256) {
            int m = e / 72, kk = e - m * 72;
            int ciL = kk / 9, tap = kk - ciL * 9;
            float v = wt[((size_t)(ocb + m) * CIN + ci0 + ciL) * 9 + tap];
            uint32_t hi = f2tf32(v);
            s_Ah[m * SAS + kk] = hi;
            s_Al[m * SAS + kk] = f2tf32(v - __uint_as_float(hi));
        }
        // stage input (hi/lo): 8 ch x 3 rows x 258 cols.
        // norm+ReLU applied ONLY in-bounds; zero-pad stays exactly zero.
        for (int e = tid; e < 8 * 3 * 258; e += 256) {
            int ciL = e / 774;
            int rem = e - ciL * 774;
            int r = rem / 258, cc = rem - r * 258;
            int gy = y + r - 1, gx = x0 + cc - 1;
            int c = ci0 + ciL;
            float v = 0.f;
            if (gy >= 0 && gy < HH && gx >= 0 && gx < WW) {
                v = in[(size_t)c * HW + gy * WW + gx];
                v = fmaxf(0.f, fmaf(v, sc[c], sh[c]));
            }
            uint32_t hi = f2tf32(v);
            int o = (ciL * 3 + r) * SRS + cc;
            s_rh[o] = hi;
            s_rl[o] = f2tf32(v - __uint_as_float(hi));
        }
        __syncthreads();

#pragma unroll
        for (int ks = 0; ks < 9; ks++) {
            const int kc1 = ks * 8 + tig, kc2 = kc1 + 4;
            uint32_t ah[2][4], al[2][4];
#pragma unroll
            for (int mf = 0; mf < 2; mf++) {
                int r0 = (mf * 16 + g) * SAS, r1 = (mf * 16 + g + 8) * SAS;
                ah[mf][0] = s_Ah[r0 + kc1];
                ah[mf][1] = s_Ah[r1 + kc1];
                ah[mf][2] = s_Ah[r0 + kc2];
                ah[mf][3] = s_Ah[r1 + kc2];
                al[mf][0] = s_Al[r0 + kc1];
                al[mf][1] = s_Al[r1 + kc1];
                al[mf][2] = s_Al[r0 + kc2];
                al[mf][3] = s_Al[r1 + kc2];
            }
            const int nb = w * 32 + g;
#pragma unroll
            for (int nf = 0; nf < 4; nf++) {
                int o1 = off1[ks] + nb + nf * 8;
                int o2 = off2[ks] + nb + nf * 8;
                uint32_t b0h = s_rh[o1], b1h = s_rh[o2];
                uint32_t b0l = s_rl[o1], b1l = s_rl[o2];
                // hi*hi + hi*lo + lo*hi
                mma_tf32(acc[0][nf], ah[0], b0h, b1h);
                mma_tf32(acc[0][nf], ah[0], b0l, b1l);
                mma_tf32(acc[0][nf], al[0], b0h, b1h);
                mma_tf32(acc[1][nf], ah[1], b0h, b1h);
                mma_tf32(acc[1][nf], ah[1], b0l, b1l);
                mma_tf32(acc[1][nf], al[1], b0h, b1h);
            }
        }
    }

    // epilogue: c0/c1 -> row g, cols 2*tig,2*tig+1 ; c2/c3 -> row g+8
#pragma unroll
    for (int mf = 0; mf < 2; mf++) {
        int oc0 = ocb + mf * 16 + g, oc1 = oc0 + 8;
        float bv0 = bias[oc0], bv1 = bias[oc1];
#pragma unroll
        for (int nf = 0; nf < 4; nf++) {
            int x = x0 + w * 32 + nf * 8 + tig * 2;
            float2 v0 = make_float2(acc[mf][nf][0] + bv0, acc[mf][nf][1] + bv0);
            float2 v1 = make_float2(acc[mf][nf][2] + bv1, acc[mf][nf][3] + bv1);
            *reinterpret_cast<float2*>(&out[(size_t)oc0 * HW + y * WW + x]) = v0;
            *reinterpret_cast<float2*>(&out[(size_t)oc1 * HW + y * WW + x]) = v1;
        }
    }
}

// ---------------- GroupNorm stats (sum / sumsq per group) ------------------
__global__ void gn_stats_kernel(const float* __restrict__ buf, int cpg, int layer) {
    __shared__ float sb[256];
    __shared__ float sq[256];
    const int c = blockIdx.x, slice = blockIdx.y;
    const float4* p = reinterpret_cast<const float4*>(buf + (size_t)c * HW + slice * 16384);
    float s = 0.f, q = 0.f;
    for (int e = threadIdx.x; e < 4096; e += 256) {
        float4 v = p[e];
        s += v.x + v.y + v.z + v.w;
        q += v.x * v.x + v.y * v.y + v.z * v.z + v.w * v.w;
    }
    sb[threadIdx.x] = s; sq[threadIdx.x] = q;
    __syncthreads();
    for (int st = 128; st > 0; st >>= 1) {
        if (threadIdx.x < st) {
            sb[threadIdx.x] += sb[threadIdx.x + st];
            sq[threadIdx.x] += sq[threadIdx.x + st];
        }
        __syncthreads();
    }
    if (threadIdx.x == 0) {
        int g = c / cpg;
        atomicAdd(&g_gs[layer][g], (double)sb[0]);
        atomicAdd(&g_gq[layer][g], (double)sq[0]);
    }
}

__global__ void gn_finalize_kernel(const float* __restrict__ gamma,
                                   const float* __restrict__ beta,
                                   int C, int cpg, int layer) {
    int c = threadIdx.x;
    if (c < C) {
        int g = c / cpg;
        double n = (double)cpg * (double)HW;
        double m = g_gs[layer][g] / n;
        double var = g_gq[layer][g] / n - m * m;
        float rs = (float)(1.0 / sqrt(var + 1e-5));
        float s = gamma[c] * rs;
        g_scaleL[layer * 128 + c] = s;
        g_shiftL[layer * 128 + c] = beta[c] - (float)m * s;
    }
}

// materialized normalize + ReLU (layer 3 output only)
__global__ void norm_relu_kernel(float* __restrict__ buf,
                                 const float* __restrict__ sc,
                                 const float* __restrict__ sh, int total4) {
    float4* b4 = reinterpret_cast<float4*>(buf);
    for (int i = blockIdx.x * blockDim.x + threadIdx.x; i < total4;
         i += gridDim.x * blockDim.x) {
        int c = i >> 16;
        float s = sc[c], h = sh[c];
        float4 v = b4[i];
        v.x = fmaxf(0.f, fmaf(v.x, s, h));
        v.y = fmaxf(0.f, fmaf(v.y, s, h));
        v.z = fmaxf(0.f, fmaf(v.z, s, h));
        v.w = fmaxf(0.f, fmaf(v.w, s, h));
        b4[i] = v;
    }
}

// ---------------- global avg pool over f (128 ch) --------------------------
__global__ void pool_kernel(const float* __restrict__ f) {
    __shared__ float sb[256];
    const int c = blockIdx.x;
    const float4* p = reinterpret_cast<const float4*>(f + (size_t)c * HW);
    float s = 0.f;
    for (int i = threadIdx.x; i < HW / 4; i += 256) {
        float4 v = p[i];
        s += v.x + v.y + v.z + v.w;
    }
    sb[threadIdx.x] = s;
    __syncthreads();
    for (int st = 128; st > 0; st >>= 1) {
        if (threadIdx.x < st) sb[threadIdx.x] += sb[threadIdx.x + st];
        __syncthreads();
    }
    if (threadIdx.x == 0) g_pooled[c] = sb[0] * (1.0f / (float)HW);
}

__global__ void value_kernel(const float* __restrict__ vw1, const float* __restrict__ vb1,
                             const float* __restrict__ vw2, const float* __restrict__ vb2,
                             float* __restrict__ out) {
    __shared__ float h[64];
    int t = threadIdx.x;
    float s = vb1[t];
    for (int k = 0; k < 128; k++) s = fmaf(g_pooled[k], vw1[k * 64 + t], s);
    h[t] = fmaxf(s, 0.f);
    __syncthreads();
    if (t == 0) {
        float v = vb2[0];
        for (int k = 0; k < 64; k++) v = fmaf(h[k], vw2[k], v);
        out[262146] = v;
    }
}

// ---------------- MLP1: patch gather + (1152 -> 256) -----------------------
__global__ void mlp1_kernel(const float* __restrict__ f,
                            const int* __restrict__ ci_, const int* __restrict__ cj_,
                            const float* __restrict__ fw1, const float* __restrict__ fb1) {
    extern __shared__ float sp[];   // [k][cell] : sp[k*16 + cc]
    const int t = threadIdx.x;
    const int base = blockIdx.x * 16;

    for (int idx = t; idx < 16 * 1152; idx += 256) {
        int cc = idx / 1152;
        int k  = idx - cc * 1152;
        int c  = k / 9;
        int rr = k - c * 9;
        int r  = rr / 3, s2 = rr - r * 3;
        int y = ci_[base + cc] - 1 + r;
        int x = cj_[base + cc] - 1 + s2;
        float v = 0.f;
        if (y >= 0 && y < HH && x >= 0 && x < WW)
            v = f[(size_t)c * HW + y * WW + x];
        sp[k * 16 + cc] = v;
    }
    __syncthreads();

    float acc[16];
#pragma unroll
    for (int cc = 0; cc < 16; cc++) acc[cc] = 0.f;

    for (int k = 0; k < 1152; k++) {
        float wv = fw1[k * 256 + t];
        const float4* s4 = reinterpret_cast<const float4*>(sp + k * 16);
        float4 a0 = s4[0], a1 = s4[1], a2 = s4[2], a3 = s4[3];
        acc[0]  = fmaf(a0.x, wv, acc[0]);  acc[1]  = fmaf(a0.y, wv, acc[1]);
        acc[2]  = fmaf(a0.z, wv, acc[2]);  acc[3]  = fmaf(a0.w, wv, acc[3]);
        acc[4]  = fmaf(a1.x, wv, acc[4]);  acc[5]  = fmaf(a1.y, wv, acc[5]);
        acc[6]  = fmaf(a1.z, wv, acc[6]);  acc[7]  = fmaf(a1.w, wv, acc[7]);
        acc[8]  = fmaf(a2.x, wv, acc[8]);  acc[9]  = fmaf(a2.y, wv, acc[9]);
        acc[10] = fmaf(a2.z, wv, acc[10]); acc[11] = fmaf(a2.w, wv, acc[11]);
        acc[12] = fmaf(a3.x, wv, acc[12]); acc[13] = fmaf(a3.y, wv, acc[13]);
        acc[14] = fmaf(a3.z, wv, acc[14]); acc[15] = fmaf(a3.w, wv, acc[15]);
    }
    float bv = fb1[t];
#pragma unroll
    for (int cc = 0; cc < 16; cc++)
        g_h1[(size_t)(base + cc) * 256 + t] = fmaxf(acc[cc] + bv, 0.f);
}

// ---------------- MLP2: (256 -> 128) ---------------------------------------
__global__ void mlp2_kernel(const float* __restrict__ fw2, const float* __restrict__ fb2) {
    __shared__ float sh1[256 * 16];
    const int t = threadIdx.x;
    const int base = blockIdx.x * 16;
    for (int idx = t; idx < 16 * 256; idx += 128) {
        int cc = idx >> 8;
        int k  = idx & 255;
        sh1[k * 16 + cc] = g_h1[(size_t)(base + cc) * 256 + k];
    }
    __syncthreads();

    float acc[16];
#pragma unroll
    for (int cc = 0; cc < 16; cc++) acc[cc] = 0.f;

    for (int k = 0; k < 256; k++) {
        float wv = fw2[k * 128 + t];
        const float4* s4 = reinterpret_cast<const float4*>(sh1 + k * 16);
        float4 a0 = s4[0], a1 = s4[1], a2 = s4[2], a3 = s4[3];
        acc[0]  = fmaf(a0.x, wv, acc[0]);  acc[1]  = fmaf(a0.y, wv, acc[1]);
        acc[2]  = fmaf(a0.z, wv, acc[2]);  acc[3]  = fmaf(a0.w, wv, acc[3]);
        acc[4]  = fmaf(a1.x, wv, acc[4]);  acc[5]  = fmaf(a1.y, wv, acc[5]);
        acc[6]  = fmaf(a1.z, wv, acc[6]);  acc[7]  = fmaf(a1.w, wv, acc[7]);
        acc[8]  = fmaf(a2.x, wv, acc[8]);  acc[9]  = fmaf(a2.y, wv, acc[9]);
        acc[10] = fmaf(a2.z, wv, acc[10]); acc[11] = fmaf(a2.w, wv, acc[11]);
        acc[12] = fmaf(a3.x, wv, acc[12]); acc[13] = fmaf(a3.y, wv, acc[13]);
        acc[14] = fmaf(a3.z, wv, acc[14]); acc[15] = fmaf(a3.w, wv, acc[15]);
    }
    float bv = fb2[t];
#pragma unroll
    for (int cc = 0; cc < 16; cc++)
        g_sh[(size_t)(base + cc) * 128 + t] = fmaxf(acc[cc] + bv, 0.f);
}

// ---------------- heads ----------------------------------------------------
__global__ void heads_kernel(const int* __restrict__ ci_, const int* __restrict__ cj_,
                             const int* __restrict__ act,
                             const float* __restrict__ bw, const float* __restrict__ bb,
                             const float* __restrict__ iw, const float* __restrict__ ib,
                             const float* __restrict__ tw, const float* __restrict__ tb,
                             float* __restrict__ out) {
    __shared__ float ssh[64][129];
    __shared__ float swb[512], swi[512], swt[512];
    __shared__ float red[256];
    const int t = threadIdx.x;
    const int base = blockIdx.x * 64;

    for (int idx = t; idx < 64 * 128; idx += 256) {
        int cc = idx >> 7, k = idx & 127;
        ssh[cc][k] = g_sh[(size_t)(base + cc) * 128 + k];
    }
    for (int idx = t; idx < 512; idx += 256) {
        swb[idx] = bw[idx]; swi[idx] = iw[idx]; swt[idx] = tw[idx];
    }
    __syncthreads();

    const int cell = t >> 2, j = t & 3;
    float sb = bb[j], si = ib[j], st = tb[j];
    for (int k = 0; k < 128; k++) {
        float v = ssh[cell][k];
        sb = fmaf(v, swb[k * 4 + j], sb);
        si = fmaf(v, swi[k * 4 + j], si);
        st = fmaf(v, swt[k * 4 + j], st);
    }
    const int gcell = base + cell;
    out[262147 + gcell * 4 + j] = si;
    out[294915 + gcell * 4 + j] = st;

    float p = 1.f / (1.f + expf(-sb));
    p = fminf(fmaxf(p, 1e-7f), 1.f - 1e-7f);
    float a = (float)act[gcell * 4 + j];
    float lp = a * logf(p) + (1.f - a) * logf(1.f - p);
    float en = -(p * logf(p) + (1.f - p) * logf(1.f - p));

    const int di4[4] = {-1, 0, 1, 0};
    const int dj4[4] = {0, 1, 0, -1};
    int ii = ci_[gcell], jj = cj_[gcell];
    int ni = ii + di4[j], nj = jj + dj4[j];
    if (a > 0.5f && ni >= 0 && ni < HH && nj >= 0 && nj < WW)
        out[ni * WW + nj] = 1.0f;

    red[t] = lp;
    __syncthreads();
    for (int s = 128; s > 0; s >>= 1) {
        if (t < s) red[t] += red[t + s];
        __syncthreads();
    }
    if (t == 0) atomicAdd(&out[262144], red[0]);
    __syncthreads();
    red[t] = en;
    __syncthreads();
    for (int s = 128; s > 0; s >>= 1) {
        if (t < s) red[t] += red[t + s];
        __syncthreads();
    }
    if (t == 0) atomicAdd(&out[262145], red[0]);
}

// ---------------- launch ----------------------------------------------------
extern "C" void kernel_launch(void* const* d_in, const int* in_sizes, int n_in,
                              void* d_out, int out_size) {
    const float* x      = (const float*)d_in[0];
    const int*   cell_i = (const int*)d_in[1];
    const int*   cell_j = (const int*)d_in[2];
    const int*   action = (const int*)d_in[3];
    const float* w1 = (const float*)d_in[4];
    const float* b1 = (const float*)d_in[5];
    const float* g1 = (const float*)d_in[6];
    const float* be1 = (const float*)d_in[7];
    const float* w2 = (const float*)d_in[8];
    const float* b2 = (const float*)d_in[9];
    const float* g2 = (const float*)d_in[10];
    const float* be2 = (const float*)d_in[11];
    const float* w3 = (const float*)d_in[12];
    const float* b3 = (const float*)d_in[13];
    const float* g3 = (const float*)d_in[14];
    const float* be3 = (const float*)d_in[15];
    const float* fw1 = (const float*)d_in[16];
    const float* fb1 = (const float*)d_in[17];
    const float* fw2 = (const float*)d_in[18];
    const float* fb2 = (const float*)d_in[19];
    const float* bw = (const float*)d_in[20];
    const float* bb = (const float*)d_in[21];
    const float* iw = (const float*)d_in[22];
    const float* ib = (const float*)d_in[23];
    const float* tw = (const float*)d_in[24];
    const float* tb = (const float*)d_in[25];
    const float* vw1 = (const float*)d_in[26];
    const float* vb1 = (const float*)d_in[27];
    const float* vw2 = (const float*)d_in[28];
    const float* vb2 = (const float*)d_in[29];
    float* out = (float*)d_out;

    float* buf1; cudaGetSymbolAddress((void**)&buf1, g_buf1);
    float* buf2; cudaGetSymbolAddress((void**)&buf2, g_buf2);
    float* buf3; cudaGetSymbolAddress((void**)&buf3, g_buf3);
    float* scL;  cudaGetSymbolAddress((void**)&scL, g_scaleL);
    float* shL;  cudaGetSymbolAddress((void**)&shL, g_shiftL);

    zero_kernel<<<1025, 256>>>(out);

    // layer 1: 14 -> 48 direct fp32, GN(6)
    conv3x3_kernel<14, 16><<<dim3(16, 16, 3), dim3(32, 8)>>>(x, w1, b1, buf1);
    gn_stats_kernel<<<dim3(48, 16), 256>>>(buf1, 8, 0);
    gn_finalize_kernel<<<1, 128>>>(g1, be1, 48, 8, 0);

    // layer 2: 48 -> 96 tf32x3 mma, input norm(l0)+relu fused into staging
    cudaFuncSetAttribute(conv_mma_kernel<48>,
                         cudaFuncAttributeMaxDynamicSharedMemorySize, SMEM_MMA_BYTES);
    conv_mma_kernel<48><<<dim3(2, 512, 3), 256, SMEM_MMA_BYTES>>>(buf1, w2, b2, scL, shL, buf2);
    gn_stats_kernel<<<dim3(96, 16), 256>>>(buf2, 8, 1);
    gn_finalize_kernel<<<1, 128>>>(g2, be2, 96, 8, 1);

    // layer 3: 96 -> 128 tf32x3 mma, input norm(l1)+relu fused
    cudaFuncSetAttribute(conv_mma_kernel<96>,
                         cudaFuncAttributeMaxDynamicSharedMemorySize, SMEM_MMA_BYTES);
    conv_mma_kernel<96><<<dim3(2, 512, 4), 256, SMEM_MMA_BYTES>>>(buf2, w3, b3, scL + 128, shL + 128, buf3);
    gn_stats_kernel<<<dim3(128, 16), 256>>>(buf3, 8, 2);
    gn_finalize_kernel<<<1, 128>>>(g3, be3, 128, 8, 2);
    norm_relu_kernel<<<2048, 256>>>(buf3, scL + 256, shL + 256, 128 * HW / 4);

    // value head
    pool_kernel<<<128, 256>>>(buf3);
    value_kernel<<<1, 64>>>(vw1, vb1, vw2, vb2, out);

    // per-cell MLP
    cudaFuncSetAttribute(mlp1_kernel, cudaFuncAttributeMaxDynamicSharedMemorySize, 73728);
    mlp1_kernel<<<512, 256, 73728>>>(buf3, cell_i, cell_j, fw1, fb1);
    mlp2_kernel<<<512, 128>>>(fw2, fb2);
    heads_kernel<<<128, 256>>>(cell_i, cell_j, action, bw, bb, iw, ib, tw, tb, out);
}

// round 13
// speedup vs baseline: 1.2037x; 1.1556x over previous
#include <cuda_runtime.h>
#include <stdint.h>
#include <math.h>

#define HH 512
#define WW 512
#define HW 262144
#define NC 8192

// ---------------- scratch (device globals; no allocation allowed) ----------
__device__ float  g_buf1[48  * HW];
__device__ float  g_buf2[96  * HW];
__device__ float  g_buf3[128 * HW];
__device__ float  g_h1[NC * 256];
__device__ float  g_sh[NC * 128];
__device__ double g_gs[3][16];
__device__ double g_gq[3][16];
__device__ float  g_scaleL[3 * 128];
__device__ float  g_shiftL[3 * 128];
__device__ float  g_pooled[128];

// ---------------- zero-init ------------------------------------------------
__global__ void zero_kernel(float* __restrict__ out) {
    int i = blockIdx.x * blockDim.x + threadIdx.x;
    if (i < 262147) out[i] = 0.f;
    if (i < 48) {
        ((double*)g_gs)[i] = 0.0;
        ((double*)g_gq)[i] = 0.0;
    }
}

// ---------------- direct 3x3 conv (layer 1 only: 14 -> 48) -----------------
template<int CIN, int OCB>
__launch_bounds__(256)
__global__ void conv3x3_kernel(const float* __restrict__ in,
                               const float* __restrict__ wt,
                               const float* __restrict__ bias,
                               float* __restrict__ out) {
    __shared__ float s_in[8][34][34];
    __shared__ float s_w[OCB][72];
    const int tx = threadIdx.x, ty = threadIdx.y;
    const int tid = ty * 32 + tx;
    const int x0 = blockIdx.x * 32, y0 = blockIdx.y * 32;
    const int ocb = blockIdx.z * OCB;

    float acc[4][OCB];
#pragma unroll
    for (int p = 0; p < 4; p++)
#pragma unroll
        for (int o = 0; o < OCB; o++) acc[p][o] = 0.f;

    for (int c0 = 0; c0 < CIN; c0 += 8) {
        const int cc = (CIN - c0 < 8) ? (CIN - c0) : 8;
        for (int idx = tid; idx < 8 * 34 * 34; idx += 256) {
            int ci  = idx / 1156;
            int rem = idx - ci * 1156;
            int r = rem / 34, s = rem - r * 34;
            float v = 0.f;
            int gy = y0 + r - 1, gx = x0 + s - 1;
            if (ci < cc && gy >= 0 && gy < HH && gx >= 0 && gx < WW)
                v = in[(size_t)(c0 + ci) * HW + gy * WW + gx];
            s_in[ci][r][s] = v;
        }
        for (int idx = tid; idx < OCB * 72; idx += 256) {
            int o = idx / 72;
            int rem = idx - o * 72;
            int ci = rem / 9;
            int k = rem - ci * 9;
            float v = 0.f;
            if (ci < cc)
                v = wt[((size_t)(ocb + o) * CIN + c0 + ci) * 9 + k];
            s_w[o][rem] = v;
        }
        __syncthreads();

        for (int ci = 0; ci < 8; ci++) {
#pragma unroll
            for (int k = 0; k < 9; k++) {
                const int dy = k / 3, dx = k - dy * 3;
                float xv[4];
#pragma unroll
                for (int p = 0; p < 4; p++)
                    xv[p] = s_in[ci][ty * 4 + p + dy][tx + dx];
#pragma unroll
                for (int o = 0; o < OCB; o++) {
                    float wv = s_w[o][ci * 9 + k];
#pragma unroll
                    for (int p = 0; p < 4; p++)
                        acc[p][o] = fmaf(xv[p], wv, acc[p][o]);
                }
            }
        }
        __syncthreads();
    }

#pragma unroll
    for (int o = 0; o < OCB; o++) {
        float bv = bias[ocb + o];
#pragma unroll
        for (int p = 0; p < 4; p++) {
            int y = y0 + ty * 4 + p;
            out[(size_t)(ocb + o) * HW + y * WW + x0 + tx] = acc[p][o] + bv;
        }
    }
}

// ---------------- tf32x3 mma implicit-GEMM conv (layers 2,3) ---------------
// Split-precision tf32x3; GN finalize folded into the kernel (reads g_gs/g_gq
// for `layer` and computes per-channel scale/shift once into smem).
// Each CTA computes TWO output rows (y0, y0+1) x 256 px x 32 oc: stages
// 4 input rows per channel, reused for both output rows.
#define SRS 267   // im2col row stride (words)
#define SAS 76    // weight row stride (words)
#define SMEM_MMA_BYTES ((2 * 32 * SAS + 2 * 8 * 4 * SRS) * 4)

__device__ __forceinline__ void mma_tf32(float* c, const uint32_t* a,
                                         uint32_t b0, uint32_t b1) {
    asm volatile(
        "mma.sync.aligned.m16n8k8.row.col.f32.tf32.tf32.f32 "
        "{%0,%1,%2,%3}, {%4,%5,%6,%7}, {%8,%9}, {%0,%1,%2,%3};"
        : "+f"(c[0]), "+f"(c[1]), "+f"(c[2]), "+f"(c[3])
        : "r"(a[0]), "r"(a[1]), "r"(a[2]), "r"(a[3]), "r"(b0), "r"(b1));
}

__device__ __forceinline__ uint32_t f2tf32(float v) {
    uint32_t u;
    asm("cvt.rna.tf32.f32 %0, %1;" : "=r"(u) : "f"(v));
    return u;
}

template<int CIN>
__launch_bounds__(256, 2)
__global__ void conv_mma_kernel(const float* __restrict__ in,
                                const float* __restrict__ wt,
                                const float* __restrict__ bias,
                                const float* __restrict__ gamma,
                                const float* __restrict__ beta,
                                int layer,
                                float* __restrict__ out) {
    extern __shared__ uint32_t smem_u[];
    uint32_t* s_Ah = smem_u;                       // [32][SAS]
    uint32_t* s_Al = s_Ah + 32 * SAS;
    uint32_t* s_rh = s_Al + 32 * SAS;              // [8*4][SRS]
    uint32_t* s_rl = s_rh + 8 * 4 * SRS;
    __shared__ float s_sc[CIN > 96 ? CIN : 96];
    __shared__ float s_sh[CIN > 96 ? CIN : 96];

    const int tid = threadIdx.x;
    const int lane = tid & 31, w = tid >> 5;
    const int g = lane >> 2, tig = lane & 3;
    const int y0 = blockIdx.y * 2, x0 = blockIdx.x * 256, ocb = blockIdx.z * 32;

    // GN finalize for the input layer (per-channel scale/shift), once
    if (tid < CIN) {
        int gi = tid >> 3;                 // cpg = 8 for all layers
        double n = 8.0 * (double)HW;
        double m = g_gs[layer][gi] / n;
        double var = g_gq[layer][gi] / n - m * m;
        float rs = (float)(1.0 / sqrt(var + 1e-5));
        float s = gamma[tid] * rs;
        s_sc[tid] = s;
        s_sh[tid] = beta[tid] - (float)m * s;
    }

    // per-thread im2col smem offsets (row stride 4 per channel); output row 1
    // uses the same offsets + SRS (dy shifted by one staged row).
    int off1[9], off2[9];
#pragma unroll
    for (int ks = 0; ks < 9; ks++) {
        int k1 = ks * 8 + tig, k2 = k1 + 4;
        int c1 = k1 / 9, t1 = k1 - c1 * 9, dy1 = t1 / 3, dx1 = t1 - dy1 * 3;
        int c2 = k2 / 9, t2 = k2 - c2 * 9, dy2 = t2 / 3, dx2 = t2 - dy2 * 3;
        off1[ks] = (c1 * 4 + dy1) * SRS + dx1;
        off2[ks] = (c2 * 4 + dy2) * SRS + dx2;
    }

    float acc[2][2][4][4];
#pragma unroll
    for (int rr = 0; rr < 2; rr++)
#pragma unroll
        for (int mf = 0; mf < 2; mf++)
#pragma unroll
            for (int nf = 0; nf < 4; nf++)
#pragma unroll
                for (int e = 0; e < 4; e++) acc[rr][mf][nf][e] = 0.f;

    for (int ci0 = 0; ci0 < CIN; ci0 += 8) {
        __syncthreads();
        // stage weights (hi/lo): 32 oc x 72 k
        for (int e = tid; e < 32 * 72; e += 256) {
            int m = e / 72, kk = e - m * 72;
            int ciL = kk / 9, tap = kk - ciL * 9;
            float v = wt[((size_t)(ocb + m) * CIN + ci0 + ciL) * 9 + tap];
            uint32_t hi = f2tf32(v);
            s_Ah[m * SAS + kk] = hi;
            s_Al[m * SAS + kk] = f2tf32(v - __uint_as_float(hi));
        }
        // stage input (hi/lo): 8 ch x 4 rows x 258 cols; norm+ReLU ONLY
        // in-bounds (zero-pad stays exactly zero).
        for (int e = tid; e < 8 * 4 * 258; e += 256) {
            int ciL = e / 1032;
            int rem = e - ciL * 1032;
            int r = rem / 258, cc = rem - r * 258;
            int gy = y0 + r - 1, gx = x0 + cc - 1;
            int c = ci0 + ciL;
            float v = 0.f;
            if (gy >= 0 && gy < HH && gx >= 0 && gx < WW) {
                v = in[(size_t)c * HW + gy * WW + gx];
                v = fmaxf(0.f, fmaf(v, s_sc[c], s_sh[c]));
            }
            uint32_t hi = f2tf32(v);
            int o = (ciL * 4 + r) * SRS + cc;
            s_rh[o] = hi;
            s_rl[o] = f2tf32(v - __uint_as_float(hi));
        }
        __syncthreads();

#pragma unroll
        for (int ks = 0; ks < 9; ks++) {
            const int kc1 = ks * 8 + tig, kc2 = kc1 + 4;
            uint32_t ah[2][4], al[2][4];
#pragma unroll
            for (int mf = 0; mf < 2; mf++) {
                int r0 = (mf * 16 + g) * SAS, r1 = (mf * 16 + g + 8) * SAS;
                ah[mf][0] = s_Ah[r0 + kc1];
                ah[mf][1] = s_Ah[r1 + kc1];
                ah[mf][2] = s_Ah[r0 + kc2];
                ah[mf][3] = s_Ah[r1 + kc2];
                al[mf][0] = s_Al[r0 + kc1];
                al[mf][1] = s_Al[r1 + kc1];
                al[mf][2] = s_Al[r0 + kc2];
                al[mf][3] = s_Al[r1 + kc2];
            }
            const int nb = w * 32 + g;
#pragma unroll
            for (int nf = 0; nf < 4; nf++) {
                int o1 = off1[ks] + nb + nf * 8;
                int o2 = off2[ks] + nb + nf * 8;
#pragma unroll
                for (int rr = 0; rr < 2; rr++) {
                    uint32_t b0h = s_rh[o1 + rr * SRS], b1h = s_rh[o2 + rr * SRS];
                    uint32_t b0l = s_rl[o1 + rr * SRS], b1l = s_rl[o2 + rr * SRS];
                    mma_tf32(acc[rr][0][nf], ah[0], b0h, b1h);
                    mma_tf32(acc[rr][0][nf], ah[0], b0l, b1l);
                    mma_tf32(acc[rr][0][nf], al[0], b0h, b1h);
                    mma_tf32(acc[rr][1][nf], ah[1], b0h, b1h);
                    mma_tf32(acc[rr][1][nf], ah[1], b0l, b1l);
                    mma_tf32(acc[rr][1][nf], al[1], b0h, b1h);
                }
            }
        }
    }

    // epilogue: c0/c1 -> row g, cols 2*tig,2*tig+1 ; c2/c3 -> row g+8
#pragma unroll
    for (int rr = 0; rr < 2; rr++) {
        int y = y0 + rr;
#pragma unroll
        for (int mf = 0; mf < 2; mf++) {
            int oc0 = ocb + mf * 16 + g, oc1 = oc0 + 8;
            float bv0 = bias[oc0], bv1 = bias[oc1];
#pragma unroll
            for (int nf = 0; nf < 4; nf++) {
                int x = x0 + w * 32 + nf * 8 + tig * 2;
                float2 v0 = make_float2(acc[rr][mf][nf][0] + bv0,
                                        acc[rr][mf][nf][1] + bv0);
                float2 v1 = make_float2(acc[rr][mf][nf][2] + bv1,
                                        acc[rr][mf][nf][3] + bv1);
                *reinterpret_cast<float2*>(&out[(size_t)oc0 * HW + y * WW + x]) = v0;
                *reinterpret_cast<float2*>(&out[(size_t)oc1 * HW + y * WW + x]) = v1;
            }
        }
    }
}

// ---------------- GroupNorm stats (sum / sumsq per group) ------------------
__global__ void gn_stats_kernel(const float* __restrict__ buf, int cpg, int layer) {
    __shared__ float sb[256];
    __shared__ float sq[256];
    const int c = blockIdx.x, slice = blockIdx.y;
    const float4* p = reinterpret_cast<const float4*>(buf + (size_t)c * HW + slice * 16384);
    float s = 0.f, q = 0.f;
    for (int e = threadIdx.x; e < 4096; e += 256) {
        float4 v = p[e];
        s += v.x + v.y + v.z + v.w;
        q += v.x * v.x + v.y * v.y + v.z * v.z + v.w * v.w;
    }
    sb[threadIdx.x] = s; sq[threadIdx.x] = q;
    __syncthreads();
    for (int st = 128; st > 0; st >>= 1) {
        if (threadIdx.x < st) {
            sb[threadIdx.x] += sb[threadIdx.x + st];
            sq[threadIdx.x] += sq[threadIdx.x + st];
        }
        __syncthreads();
    }
    if (threadIdx.x == 0) {
        int g = c / cpg;
        atomicAdd(&g_gs[layer][g], (double)sb[0]);
        atomicAdd(&g_gq[layer][g], (double)sq[0]);
    }
}

__global__ void gn_finalize_kernel(const float* __restrict__ gamma,
                                   const float* __restrict__ beta,
                                   int C, int cpg, int layer) {
    int c = threadIdx.x;
    if (c < C) {
        int g = c / cpg;
        double n = (double)cpg * (double)HW;
        double m = g_gs[layer][g] / n;
        double var = g_gq[layer][g] / n - m * m;
        float rs = (float)(1.0 / sqrt(var + 1e-5));
        float s = gamma[c] * rs;
        g_scaleL[layer * 128 + c] = s;
        g_shiftL[layer * 128 + c] = beta[c] - (float)m * s;
    }
}

// materialized normalize + ReLU (layer 3 output only)
__global__ void norm_relu_kernel(float* __restrict__ buf,
                                 const float* __restrict__ sc,
                                 const float* __restrict__ sh, int total4) {
    float4* b4 = reinterpret_cast<float4*>(buf);
    for (int i = blockIdx.x * blockDim.x + threadIdx.x; i < total4;
         i += gridDim.x * blockDim.x) {
        int c = i >> 16;
        float s = sc[c], h = sh[c];
        float4 v = b4[i];
        v.x = fmaxf(0.f, fmaf(v.x, s, h));
        v.y = fmaxf(0.f, fmaf(v.y, s, h));
        v.z = fmaxf(0.f, fmaf(v.z, s, h));
        v.w = fmaxf(0.f, fmaf(v.w, s, h));
        b4[i] = v;
    }
}

// ---------------- global avg pool over f (128 ch) --------------------------
__global__ void pool_kernel(const float* __restrict__ f) {
    __shared__ float sb[256];
    const int c = blockIdx.x;
    const float4* p = reinterpret_cast<const float4*>(f + (size_t)c * HW);
    float s = 0.f;
    for (int i = threadIdx.x; i < HW / 4; i += 256) {
        float4 v = p[i];
        s += v.x + v.y + v.z + v.w;
    }
    sb[threadIdx.x] = s;
    __syncthreads();
    for (int st = 128; st > 0; st >>= 1) {
        if (threadIdx.x < st) sb[threadIdx.x] += sb[threadIdx.x + st];
        __syncthreads();
    }
    if (threadIdx.x == 0) g_pooled[c] = sb[0] * (1.0f / (float)HW);
}

__global__ void value_kernel(const float* __restrict__ vw1, const float* __restrict__ vb1,
                             const float* __restrict__ vw2, const float* __restrict__ vb2,
                             float* __restrict__ out) {
    __shared__ float h[64];
    int t = threadIdx.x;
    float s = vb1[t];
    for (int k = 0; k < 128; k++) s = fmaf(g_pooled[k], vw1[k * 64 + t], s);
    h[t] = fmaxf(s, 0.f);
    __syncthreads();
    if (t == 0) {
        float v = vb2[0];
        for (int k = 0; k < 64; k++) v = fmaf(h[k], vw2[k], v);
        out[262146] = v;
    }
}

// ---------------- MLP1: patch gather + (1152 -> 256) -----------------------
__global__ void mlp1_kernel(const float* __restrict__ f,
                            const int* __restrict__ ci_, const int* __restrict__ cj_,
                            const float* __restrict__ fw1, const float* __restrict__ fb1) {
    extern __shared__ float sp[];   // [k][cell] : sp[k*16 + cc]
    const int t = threadIdx.x;
    const int base = blockIdx.x * 16;

    for (int idx = t; idx < 16 * 1152; idx += 256) {
        int cc = idx / 1152;
        int k  = idx - cc * 1152;
        int c  = k / 9;
        int rr = k - c * 9;
        int r  = rr / 3, s2 = rr - r * 3;
        int y = ci_[base + cc] - 1 + r;
        int x = cj_[base + cc] - 1 + s2;
        float v = 0.f;
        if (y >= 0 && y < HH && x >= 0 && x < WW)
            v = f[(size_t)c * HW + y * WW + x];
        sp[k * 16 + cc] = v;
    }
    __syncthreads();

    float acc[16];
#pragma unroll
    for (int cc = 0; cc < 16; cc++) acc[cc] = 0.f;

    for (int k = 0; k < 1152; k++) {
        float wv = fw1[k * 256 + t];
        const float4* s4 = reinterpret_cast<const float4*>(sp + k * 16);
        float4 a0 = s4[0], a1 = s4[1], a2 = s4[2], a3 = s4[3];
        acc[0]  = fmaf(a0.x, wv, acc[0]);  acc[1]  = fmaf(a0.y, wv, acc[1]);
        acc[2]  = fmaf(a0.z, wv, acc[2]);  acc[3]  = fmaf(a0.w, wv, acc[3]);
        acc[4]  = fmaf(a1.x, wv, acc[4]);  acc[5]  = fmaf(a1.y, wv, acc[5]);
        acc[6]  = fmaf(a1.z, wv, acc[6]);  acc[7]  = fmaf(a1.w, wv, acc[7]);
        acc[8]  = fmaf(a2.x, wv, acc[8]);  acc[9]  = fmaf(a2.y, wv, acc[9]);
        acc[10] = fmaf(a2.z, wv, acc[10]); acc[11] = fmaf(a2.w, wv, acc[11]);
        acc[12] = fmaf(a3.x, wv, acc[12]); acc[13] = fmaf(a3.y, wv, acc[13]);
        acc[14] = fmaf(a3.z, wv, acc[14]); acc[15] = fmaf(a3.w, wv, acc[15]);
    }
    float bv = fb1[t];
#pragma unroll
    for (int cc = 0; cc < 16; cc++)
        g_h1[(size_t)(base + cc) * 256 + t] = fmaxf(acc[cc] + bv, 0.f);
}

// ---------------- MLP2: (256 -> 128) ---------------------------------------
__global__ void mlp2_kernel(const float* __restrict__ fw2, const float* __restrict__ fb2) {
    __shared__ float sh1[256 * 16];
    const int t = threadIdx.x;
    const int base = blockIdx.x * 16;
    for (int idx = t; idx < 16 * 256; idx += 128) {
        int cc = idx >> 8;
        int k  = idx & 255;
        sh1[k * 16 + cc] = g_h1[(size_t)(base + cc) * 256 + k];
    }
    __syncthreads();

    float acc[16];
#pragma unroll
    for (int cc = 0; cc < 16; cc++) acc[cc] = 0.f;

    for (int k = 0; k < 256; k++) {
        float wv = fw2[k * 128 + t];
        const float4* s4 = reinterpret_cast<const float4*>(sh1 + k * 16);
        float4 a0 = s4[0], a1 = s4[1], a2 = s4[2], a3 = s4[3];
        acc[0]  = fmaf(a0.x, wv, acc[0]);  acc[1]  = fmaf(a0.y, wv, acc[1]);
        acc[2]  = fmaf(a0.z, wv, acc[2]);  acc[3]  = fmaf(a0.w, wv, acc[3]);
        acc[4]  = fmaf(a1.x, wv, acc[4]);  acc[5]  = fmaf(a1.y, wv, acc[5]);
        acc[6]  = fmaf(a1.z, wv, acc[6]);  acc[7]  = fmaf(a1.w, wv, acc[7]);
        acc[8]  = fmaf(a2.x, wv, acc[8]);  acc[9]  = fmaf(a2.y, wv, acc[9]);
        acc[10] = fmaf(a2.z, wv, acc[10]); acc[11] = fmaf(a2.w, wv, acc[11]);
        acc[12] = fmaf(a3.x, wv, acc[12]); acc[13] = fmaf(a3.y, wv, acc[13]);
        acc[14] = fmaf(a3.z, wv, acc[14]); acc[15] = fmaf(a3.w, wv, acc[15]);
    }
    float bv = fb2[t];
#pragma unroll
    for (int cc = 0; cc < 16; cc++)
        g_sh[(size_t)(base + cc) * 128 + t] = fmaxf(acc[cc] + bv, 0.f);
}

// ---------------- heads ----------------------------------------------------
__global__ void heads_kernel(const int* __restrict__ ci_, const int* __restrict__ cj_,
                             const int* __restrict__ act,
                             const float* __restrict__ bw, const float* __restrict__ bb,
                             const float* __restrict__ iw, const float* __restrict__ ib,
                             const float* __restrict__ tw, const float* __restrict__ tb,
                             float* __restrict__ out) {
    __shared__ float ssh[64][129];
    __shared__ float swb[512], swi[512], swt[512];
    __shared__ float red[256];
    const int t = threadIdx.x;
    const int base = blockIdx.x * 64;

    for (int idx = t; idx < 64 * 128; idx += 256) {
        int cc = idx >> 7, k = idx & 127;
        ssh[cc][k] = g_sh[(size_t)(base + cc) * 128 + k];
    }
    for (int idx = t; idx < 512; idx += 256) {
        swb[idx] = bw[idx]; swi[idx] = iw[idx]; swt[idx] = tw[idx];
    }
    __syncthreads();

    const int cell = t >> 2, j = t & 3;
    float sb = bb[j], si = ib[j], st = tb[j];
    for (int k = 0; k < 128; k++) {
        float v = ssh[cell][k];
        sb = fmaf(v, swb[k * 4 + j], sb);
        si = fmaf(v, swi[k * 4 + j], si);
        st = fmaf(v, swt[k * 4 + j], st);
    }
    const int gcell = base + cell;
    out[262147 + gcell * 4 + j] = si;
    out[294915 + gcell * 4 + j] = st;

    float p = 1.f / (1.f + expf(-sb));
    p = fminf(fmaxf(p, 1e-7f), 1.f - 1e-7f);
    float a = (float)act[gcell * 4 + j];
    float lp = a * logf(p) + (1.f - a) * logf(1.f - p);
    float en = -(p * logf(p) + (1.f - p) * logf(1.f - p));

    const int di4[4] = {-1, 0, 1, 0};
    const int dj4[4] = {0, 1, 0, -1};
    int ii = ci_[gcell], jj = cj_[gcell];
    int ni = ii + di4[j], nj = jj + dj4[j];
    if (a > 0.5f && ni >= 0 && ni < HH && nj >= 0 && nj < WW)
        out[ni * WW + nj] = 1.0f;

    red[t] = lp;
    __syncthreads();
    for (int s = 128; s > 0; s >>= 1) {
        if (t < s) red[t] += red[t + s];
        __syncthreads();
    }
    if (t == 0) atomicAdd(&out[262144], red[0]);
    __syncthreads();
    red[t] = en;
    __syncthreads();
    for (int s = 128; s > 0; s >>= 1) {
        if (t < s) red[t] += red[t + s];
        __syncthreads();
    }
    if (t == 0) atomicAdd(&out[262145], red[0]);
}

// ---------------- launch ----------------------------------------------------
extern "C" void kernel_launch(void* const* d_in, const int* in_sizes, int n_in,
                              void* d_out, int out_size) {
    const float* x      = (const float*)d_in[0];
    const int*   cell_i = (const int*)d_in[1];
    const int*   cell_j = (const int*)d_in[2];
    const int*   action = (const int*)d_in[3];
    const float* w1 = (const float*)d_in[4];
    const float* b1 = (const float*)d_in[5];
    const float* g1 = (const float*)d_in[6];
    const float* be1 = (const float*)d_in[7];
    const float* w2 = (const float*)d_in[8];
    const float* b2 = (const float*)d_in[9];
    const float* g2 = (const float*)d_in[10];
    const float* be2 = (const float*)d_in[11];
    const float* w3 = (const float*)d_in[12];
    const float* b3 = (const float*)d_in[13];
    const float* g3 = (const float*)d_in[14];
    const float* be3 = (const float*)d_in[15];
    const float* fw1 = (const float*)d_in[16];
    const float* fb1 = (const float*)d_in[17];
    const float* fw2 = (const float*)d_in[18];
    const float* fb2 = (const float*)d_in[19];
    const float* bw = (const float*)d_in[20];
    const float* bb = (const float*)d_in[21];
    const float* iw = (const float*)d_in[22];
    const float* ib = (const float*)d_in[23];
    const float* tw = (const float*)d_in[24];
    const float* tb = (const float*)d_in[25];
    const float* vw1 = (const float*)d_in[26];
    const float* vb1 = (const float*)d_in[27];
    const float* vw2 = (const float*)d_in[28];
    const float* vb2 = (const float*)d_in[29];
    float* out = (float*)d_out;

    float* buf1; cudaGetSymbolAddress((void**)&buf1, g_buf1);
    float* buf2; cudaGetSymbolAddress((void**)&buf2, g_buf2);
    float* buf3; cudaGetSymbolAddress((void**)&buf3, g_buf3);
    float* scL;  cudaGetSymbolAddress((void**)&scL, g_scaleL);
    float* shL;  cudaGetSymbolAddress((void**)&shL, g_shiftL);

    cudaFuncSetAttribute(conv_mma_kernel<48>,
                         cudaFuncAttributeMaxDynamicSharedMemorySize, SMEM_MMA_BYTES);
    cudaFuncSetAttribute(conv_mma_kernel<96>,
                         cudaFuncAttributeMaxDynamicSharedMemorySize, SMEM_MMA_BYTES);
    cudaFuncSetAttribute(mlp1_kernel, cudaFuncAttributeMaxDynamicSharedMemorySize, 73728);

    zero_kernel<<<1025, 256>>>(out);                                    // launch 0

    // layer 1: 14 -> 48 direct fp32
    conv3x3_kernel<14, 16><<<dim3(16, 16, 3), dim3(32, 8)>>>(x, w1, b1, buf1);  // 1
    gn_stats_kernel<<<dim3(48, 16), 256>>>(buf1, 8, 0);                         // 2

    // layer 2: 48 -> 96 tf32x3 mma, GN(L0)+ReLU fused  (ncu capture slot)
    conv_mma_kernel<48><<<dim3(2, 256, 3), 256, SMEM_MMA_BYTES>>>(              // 3
        buf1, w2, b2, g2, be2, 0, buf2);
    gn_stats_kernel<<<dim3(96, 16), 256>>>(buf2, 8, 1);                         // 4

    // layer 3: 96 -> 128 tf32x3 mma, GN(L1)+ReLU fused
    conv_mma_kernel<96><<<dim3(2, 256, 4), 256, SMEM_MMA_BYTES>>>(              // 5
        buf2, w3, b3, g3, be3, 1, buf3);
    gn_stats_kernel<<<dim3(128, 16), 256>>>(buf3, 8, 2);                        // 6
    gn_finalize_kernel<<<1, 128>>>(g3, be3, 128, 8, 2);                         // 7
    norm_relu_kernel<<<2048, 256>>>(buf3, scL + 256, shL + 256, 128 * HW / 4);  // 8

    // value head
    pool_kernel<<<128, 256>>>(buf3);
    value_kernel<<<1, 64>>>(vw1, vb1, vw2, vb2, out);

    // per-cell MLP
    mlp1_kernel<<<512, 256, 73728>>>(buf3, cell_i, cell_j, fw1, fb1);
    mlp2_kernel<<<512, 128>>>(fw2, fb2);
    heads_kernel<<<128, 256>>>(cell_i, cell_j, action, bw, bb, iw, ib, tw, tb, out);
}